// round 6
// baseline (speedup 1.0000x reference)
#include <cuda_runtime.h>
#include <cstdint>

// Per-sample dynamic-filter 3x3 VALID conv as implicit GEMM:
//   D[x=128, cout=128] += sum_{ky,kx,ci} X[b, y+ky, x+kx, ci] * W[b, ky, kx, ci, cout]
// mma.sync m16n8k8 tf32. Double-buffered SMEM, 1 barrier per K-chunk.

#define OH 126
#define CIN 128
#define COUT 128

#define A_STRIDE 36     // 32 ci + pad4
#define B_STRIDE 136    // 128 cout + pad8
#define STAGE_WORDS (128 * A_STRIDE + 32 * B_STRIDE)   // 4608 + 4352 = 8960
#define SMEM_BYTES (2 * STAGE_WORDS * 4)               // 71680

static __device__ __forceinline__ uint32_t f2tf32(float x) {
    uint32_t r;
    asm("cvt.rna.tf32.f32 %0, %1;" : "=r"(r) : "f"(x));
    return r;
}

static __device__ __forceinline__ void mma_tf32(float* c, const uint32_t* a,
                                                uint32_t b0, uint32_t b1) {
    asm volatile(
        "mma.sync.aligned.m16n8k8.row.col.f32.tf32.tf32.f32 "
        "{%0,%1,%2,%3}, {%4,%5,%6,%7}, {%8,%9}, {%0,%1,%2,%3};"
        : "+f"(c[0]), "+f"(c[1]), "+f"(c[2]), "+f"(c[3])
        : "r"(a[0]), "r"(a[1]), "r"(a[2]), "r"(a[3]), "r"(b0), "r"(b1));
}

__global__ void __launch_bounds__(256, 2) conv_mma_kernel(
    const float* __restrict__ X,    // [16,128,128,128]
    const float* __restrict__ Wt,   // [16,3,3,128,128]
    float* __restrict__ Out)        // [16,126,126,128]
{
    extern __shared__ uint32_t smem[];

    const int tid  = threadIdx.x;
    const int lane = tid & 31;
    const int warp = tid >> 5;
    const int wm   = warp & 3;     // warp tile row:  wm*32
    const int wn   = warp >> 2;    // warp tile col:  wn*64
    const int y = blockIdx.x;      // output row 0..125
    const int b = blockIdx.y;      // sample   0..15

    const float* Xb = X  + (size_t)b * (128u * 128u * 128u);
    const float* Wb = Wt + (size_t)b * (9u * 128u * 128u);

    float acc[2][8][4];
    #pragma unroll
    for (int mi = 0; mi < 2; mi++)
        #pragma unroll
        for (int ni = 0; ni < 8; ni++)
            #pragma unroll
            for (int j = 0; j < 4; j++) acc[mi][ni][j] = 0.0f;

    // chunk k -> (ky, c0, kx): k = ky*12 + (c0/32)*3 + kx  (kx inner: X line reuse)
    float4 ra[4], rb[4];

    // per-thread staging coords (constant across chunks)
    const int arow[4] = { tid >> 3, (tid + 256) >> 3, (tid + 512) >> 3, (tid + 768) >> 3 };
    const int asl  = tid & 7;

    // ---- prefetch chunk 0 into regs ----
    {
        const float* Ap = Xb + (size_t)y * (128 * 128);
        #pragma unroll
        for (int t = 0; t < 4; t++) {
            int xi = arow[t];   // kx=0
            ra[t] = *reinterpret_cast<const float4*>(Ap + (size_t)xi * CIN + asl * 4);
        }
        const float4* Bp = reinterpret_cast<const float4*>(Wb);
        #pragma unroll
        for (int t = 0; t < 4; t++) rb[t] = Bp[tid + 256 * t];
    }
    // ---- store chunk 0 -> stage 0 ----
    {
        uint32_t* sA = smem;
        uint32_t* sB = smem + 128 * A_STRIDE;
        #pragma unroll
        for (int t = 0; t < 4; t++) {
            uint32_t* p = &sA[arow[t] * A_STRIDE + asl * 4];
            p[0] = f2tf32(ra[t].x); p[1] = f2tf32(ra[t].y);
            p[2] = f2tf32(ra[t].z); p[3] = f2tf32(ra[t].w);
        }
        #pragma unroll
        for (int t = 0; t < 4; t++) {
            int idx = tid + 256 * t;
            uint32_t* p = &sB[(idx >> 5) * B_STRIDE + (idx & 31) * 4];
            p[0] = f2tf32(rb[t].x); p[1] = f2tf32(rb[t].y);
            p[2] = f2tf32(rb[t].z); p[3] = f2tf32(rb[t].w);
        }
    }
    __syncthreads();

    for (int k = 0; k < 36; k++) {
        const uint32_t* sA = smem + (k & 1) * STAGE_WORDS;
        const uint32_t* sB = sA + 128 * A_STRIDE;

        // ---- issue LDG for chunk k+1 (completes under the MMAs below) ----
        if (k < 35) {
            const int kn = k + 1;
            const int ky = kn / 12, rem = kn % 12;
            const int c0 = (rem / 3) * 32, kx = rem % 3;
            const float* Ap = Xb + (size_t)(y + ky) * (128 * 128) + c0;
            #pragma unroll
            for (int t = 0; t < 4; t++) {
                int xi = arow[t] + kx; if (xi > 127) xi = 127;  // dead rows clamp
                ra[t] = *reinterpret_cast<const float4*>(Ap + (size_t)xi * CIN + asl * 4);
            }
            const float4* Bp = reinterpret_cast<const float4*>(
                Wb + (size_t)((ky * 3 + kx) * CIN + c0) * COUT);
            #pragma unroll
            for (int t = 0; t < 4; t++) rb[t] = Bp[tid + 256 * t];
        }

        // ---- compute: 4 k-steps of m16n8k8 over the 32-ci chunk ----
        #pragma unroll
        for (int kk = 0; kk < 4; kk++) {
            const int k0 = kk * 8;
            uint32_t af[2][4];
            const int ar = wm * 32 + (lane >> 2);
            const int ac = k0 + (lane & 3);
            #pragma unroll
            for (int mi = 0; mi < 2; mi++) {
                af[mi][0] = sA[(ar + mi * 16    ) * A_STRIDE + ac    ];
                af[mi][1] = sA[(ar + mi * 16 + 8) * A_STRIDE + ac    ];
                af[mi][2] = sA[(ar + mi * 16    ) * A_STRIDE + ac + 4];
                af[mi][3] = sA[(ar + mi * 16 + 8) * A_STRIDE + ac + 4];
            }
            const int br = k0 + (lane & 3);
            const int bc = wn * 64 + (lane >> 2);
            #pragma unroll
            for (int ni = 0; ni < 8; ni++) {
                uint32_t b0 = sB[(br    ) * B_STRIDE + bc + ni * 8];
                uint32_t b1 = sB[(br + 4) * B_STRIDE + bc + ni * 8];
                mma_tf32(acc[0][ni], af[0], b0, b1);
                mma_tf32(acc[1][ni], af[1], b0, b1);
            }
        }

        // ---- store chunk k+1 into the other stage (no conflict with compute) ----
        if (k < 35) {
            uint32_t* dA = smem + ((k + 1) & 1) * STAGE_WORDS;
            uint32_t* dB = dA + 128 * A_STRIDE;
            #pragma unroll
            for (int t = 0; t < 4; t++) {
                uint32_t* p = &dA[arow[t] * A_STRIDE + asl * 4];
                p[0] = f2tf32(ra[t].x); p[1] = f2tf32(ra[t].y);
                p[2] = f2tf32(ra[t].z); p[3] = f2tf32(ra[t].w);
            }
            #pragma unroll
            for (int t = 0; t < 4; t++) {
                int idx = tid + 256 * t;
                uint32_t* p = &dB[(idx >> 5) * B_STRIDE + (idx & 31) * 4];
                p[0] = f2tf32(rb[t].x); p[1] = f2tf32(rb[t].y);
                p[2] = f2tf32(rb[t].z); p[3] = f2tf32(rb[t].w);
            }
        }
        __syncthreads();
    }

    // ---- epilogue: registers -> Out, skipping dead x rows (>=126) ----
    float* Ob = Out + ((size_t)b * OH + y) * (OH * (size_t)COUT);
    #pragma unroll
    for (int mi = 0; mi < 2; mi++) {
        const int row0 = wm * 32 + mi * 16 + (lane >> 2);
        #pragma unroll
        for (int ni = 0; ni < 8; ni++) {
            const int col = wn * 64 + ni * 8 + 2 * (lane & 3);
            if (row0 < OH) {
                float2 v = make_float2(acc[mi][ni][0], acc[mi][ni][1]);
                *reinterpret_cast<float2*>(Ob + (size_t)row0 * COUT + col) = v;
            }
            if (row0 + 8 < OH) {
                float2 v = make_float2(acc[mi][ni][2], acc[mi][ni][3]);
                *reinterpret_cast<float2*>(Ob + (size_t)(row0 + 8) * COUT + col) = v;
            }
        }
    }
}

extern "C" void kernel_launch(void* const* d_in, const int* in_sizes, int n_in,
                              void* d_out, int out_size) {
    (void)in_sizes; (void)n_in; (void)out_size;
    const float* X  = (const float*)d_in[0];
    const float* Wt = (const float*)d_in[1];
    float* out = (float*)d_out;
    cudaFuncSetAttribute(conv_mma_kernel,
                         cudaFuncAttributeMaxDynamicSharedMemorySize, SMEM_BYTES);
    conv_mma_kernel<<<dim3(OH, 16), 256, SMEM_BYTES>>>(X, Wt, out);
}

// round 11
// speedup vs baseline: 1.1521x; 1.1521x over previous
#include <cuda_runtime.h>
#include <cstdint>

// Per-sample dynamic-filter 3x3 VALID conv as implicit GEMM, mma.sync tf32.
// Pipeline: pre-pass rounds X,W to tf32 (rna) into device scratch; main kernel
// stages via cp.async (3-stage), so the hot loop has no staging regs / no cvt.

#define OH 126
#define CIN 128
#define COUT 128

#define A_STRIDE 36     // 32 ci + pad4
#define B_STRIDE 136    // 128 cout + pad8
#define A_WORDS (128 * A_STRIDE)
#define STAGE_WORDS (A_WORDS + 32 * B_STRIDE)      // 8960 words = 35840 B
#define NSTAGE 3
#define SMEM_BYTES (NSTAGE * STAGE_WORDS * 4)      // 107520 B

__device__ float g_Xr[16u * 128u * 128u * 128u];   // 134 MB scratch
__device__ float g_Wr[16u * 9u * 128u * 128u];     // 9.4 MB scratch

static __device__ __forceinline__ uint32_t f2tf32(float x) {
    uint32_t r;
    asm("cvt.rna.tf32.f32 %0, %1;" : "=r"(r) : "f"(x));
    return r;
}
static __device__ __forceinline__ void cpasync16(uint32_t s, const float* g) {
    asm volatile("cp.async.cg.shared.global [%0], [%1], 16;" :: "r"(s), "l"(g));
}
static __device__ __forceinline__ void mma_tf32(float* c, const uint32_t* a,
                                                uint32_t b0, uint32_t b1) {
    asm volatile(
        "mma.sync.aligned.m16n8k8.row.col.f32.tf32.tf32.f32 "
        "{%0,%1,%2,%3}, {%4,%5,%6,%7}, {%8,%9}, {%0,%1,%2,%3};"
        : "+f"(c[0]), "+f"(c[1]), "+f"(c[2]), "+f"(c[3])
        : "r"(a[0]), "r"(a[1]), "r"(a[2]), "r"(a[3]), "r"(b0), "r"(b1));
}

// ---- pre-pass: rna-round fp32 -> tf32-valued fp32 ----
__global__ void __launch_bounds__(256) round_kernel(const float* __restrict__ in,
                                                    float* __restrict__ out, int n4) {
    int i = blockIdx.x * blockDim.x + threadIdx.x;
    const int step = gridDim.x * blockDim.x;
    for (; i < n4; i += step) {
        float4 v = reinterpret_cast<const float4*>(in)[i];
        uint4 r;
        r.x = f2tf32(v.x); r.y = f2tf32(v.y);
        r.z = f2tf32(v.z); r.w = f2tf32(v.w);
        reinterpret_cast<uint4*>(out)[i] = r;
    }
}

__global__ void __launch_bounds__(256, 2) conv_mma_kernel(float* __restrict__ Out)
{
    extern __shared__ uint32_t smem[];
    const uint32_t sbase = (uint32_t)__cvta_generic_to_shared(smem);

    const int tid  = threadIdx.x;
    const int lane = tid & 31;
    const int warp = tid >> 5;
    const int wm   = warp & 3;     // warp tile row:  wm*32
    const int wn   = warp >> 2;    // warp tile col:  wn*64
    const int y = blockIdx.x;      // output row 0..125
    const int b = blockIdx.y;      // sample   0..15

    const float* Xb = g_Xr + (size_t)b * (128u * 128u * 128u);
    const float* Wb = g_Wr + (size_t)b * (9u * 128u * 128u);

    float acc[2][8][4];
    #pragma unroll
    for (int mi = 0; mi < 2; mi++)
        #pragma unroll
        for (int ni = 0; ni < 8; ni++)
            #pragma unroll
            for (int j = 0; j < 4; j++) acc[mi][ni][j] = 0.0f;

    // per-thread staging slots (constant): A -> 4 rows x one 16B slot; B -> 4 16B slots
    const int ar0 = tid >> 3;            // +0,32,64,96
    const int asl = tid & 7;
    const int br0 = tid >> 5;            // +0,8,16,24
    const int bsl = tid & 31;

    // chunk k -> (ky, c0, kx): k = ky*12 + (c0/32)*3 + kx  (kx inner: X line reuse)
    auto issue_stage = [&](int k, int stg) {
        const int ky = k / 12, rem = k % 12;
        const int c0 = (rem / 3) * 32, kx = rem % 3;
        const uint32_t dst = sbase + (uint32_t)(stg * STAGE_WORDS * 4);
        const float* Ap = Xb + (size_t)(y + ky) * (128 * 128) + c0 + asl * 4;
        #pragma unroll
        for (int t = 0; t < 4; t++) {
            int xi = ar0 + t * 32 + kx; if (xi > 127) xi = 127;  // dead-row clamp
            cpasync16(dst + (uint32_t)(((ar0 + t * 32) * A_STRIDE + asl * 4) * 4),
                      Ap + (size_t)xi * CIN);
        }
        const float* Bp = Wb + (size_t)((ky * 3 + kx) * CIN + c0) * COUT + bsl * 4;
        #pragma unroll
        for (int t = 0; t < 4; t++) {
            cpasync16(dst + (uint32_t)((A_WORDS + (br0 + t * 8) * B_STRIDE + bsl * 4) * 4),
                      Bp + (size_t)(br0 + t * 8) * COUT);   // src row matches dst row
        }
    };

    // prologue: stages 0,1 in flight
    issue_stage(0, 0);
    asm volatile("cp.async.commit_group;" ::: "memory");
    issue_stage(1, 1);
    asm volatile("cp.async.commit_group;" ::: "memory");

    for (int k = 0; k < 36; k++) {
        asm volatile("cp.async.wait_group 1;" ::: "memory");  // stage k resident
        __syncthreads();   // also: all warps done with buf[(k-1)%3] before refill

        if (k + 2 < 36) issue_stage(k + 2, (k + 2) % NSTAGE);
        asm volatile("cp.async.commit_group;" ::: "memory");  // (empty ok at tail)

        const uint32_t* sA = smem + (k % NSTAGE) * STAGE_WORDS;
        const uint32_t* sB = sA + A_WORDS;

        #pragma unroll
        for (int kk = 0; kk < 4; kk++) {
            const int k0 = kk * 8;
            uint32_t af[2][4];
            const int ar = wm * 32 + (lane >> 2);
            const int ac = k0 + (lane & 3);
            #pragma unroll
            for (int mi = 0; mi < 2; mi++) {
                af[mi][0] = sA[(ar + mi * 16    ) * A_STRIDE + ac    ];
                af[mi][1] = sA[(ar + mi * 16 + 8) * A_STRIDE + ac    ];
                af[mi][2] = sA[(ar + mi * 16    ) * A_STRIDE + ac + 4];
                af[mi][3] = sA[(ar + mi * 16 + 8) * A_STRIDE + ac + 4];
            }
            const int br = k0 + (lane & 3);
            const int bc = wn * 64 + (lane >> 2);
            #pragma unroll
            for (int ni = 0; ni < 8; ni++) {
                uint32_t b0 = sB[(br    ) * B_STRIDE + bc + ni * 8];
                uint32_t b1 = sB[(br + 4) * B_STRIDE + bc + ni * 8];
                mma_tf32(acc[0][ni], af[0], b0, b1);
                mma_tf32(acc[1][ni], af[1], b0, b1);
            }
        }
    }

    // ---- epilogue: registers -> Out, skipping dead x rows (>=126) ----
    float* Ob = Out + ((size_t)b * OH + y) * (OH * (size_t)COUT);
    #pragma unroll
    for (int mi = 0; mi < 2; mi++) {
        const int row0 = wm * 32 + mi * 16 + (lane >> 2);
        #pragma unroll
        for (int ni = 0; ni < 8; ni++) {
            const int col = wn * 64 + ni * 8 + 2 * (lane & 3);
            if (row0 < OH) {
                float2 v = make_float2(acc[mi][ni][0], acc[mi][ni][1]);
                *reinterpret_cast<float2*>(Ob + (size_t)row0 * COUT + col) = v;
            }
            if (row0 + 8 < OH) {
                float2 v = make_float2(acc[mi][ni][2], acc[mi][ni][3]);
                *reinterpret_cast<float2*>(Ob + (size_t)(row0 + 8) * COUT + col) = v;
            }
        }
    }
}

extern "C" void kernel_launch(void* const* d_in, const int* in_sizes, int n_in,
                              void* d_out, int out_size) {
    (void)in_sizes; (void)n_in; (void)out_size;
    const float* X  = (const float*)d_in[0];
    const float* Wt = (const float*)d_in[1];
    float* out = (float*)d_out;

    float *xr, *wr;
    cudaGetSymbolAddress((void**)&xr, g_Xr);
    cudaGetSymbolAddress((void**)&wr, g_Wr);

    round_kernel<<<2048, 256>>>(X,  xr, (16 * 128 * 128 * 128) / 4);
    round_kernel<<<512,  256>>>(Wt, wr, (16 * 9 * 128 * 128) / 4);

    cudaFuncSetAttribute(conv_mma_kernel,
                         cudaFuncAttributeMaxDynamicSharedMemorySize, SMEM_BYTES);
    conv_mma_kernel<<<dim3(OH, 16), 256, SMEM_BYTES>>>(out);
}

// round 12
// speedup vs baseline: 1.8251x; 1.5842x over previous
#include <cuda_runtime.h>
#include <cuda_fp16.h>
#include <cstdint>

// Per-sample dynamic-filter 3x3 VALID conv as implicit GEMM, fp16 HMMA:
// mma.sync.m16n8k16.f32.f16.f16.f32 (fp16 mantissa == tf32 mantissa, so same
// accuracy as the tf32 path, at half the mma instructions and half the bytes).
// Pre-pass converts X -> fp16 flat and W -> ci-pair-interleaved fp16 words.

#define OH 126
#define CIN 128
#define COUT 128

#define A_STRIDE 20                      // words per A row (16 data + 4 pad)
#define B_STRIDE 136                     // words per B cp-row (128 data + 8 pad)
#define A_WORDS (128 * A_STRIDE)         // 2560
#define B_WORDS (16 * B_STRIDE)          // 2176
#define STAGE_WORDS (A_WORDS + B_WORDS)  // 4736 words = 18944 B
#define NSTAGE 3
#define SMEM_BYTES (NSTAGE * STAGE_WORDS * 4)   // 56832 B

__device__ __half  g_Xh[16u * 128u * 128u * 128u];   // 67 MB fp16 X
__device__ uint32_t g_Wc[16u * 9u * 64u * 128u];     // 4.7 MB ci-pair words

static __device__ __forceinline__ uint32_t packh2(float a, float b) {
    __half2 h = __floats2half2_rn(a, b);     // low = a (smaller ci)
    return *reinterpret_cast<uint32_t*>(&h);
}
static __device__ __forceinline__ void cpasync16(uint32_t s, const void* g) {
    asm volatile("cp.async.cg.shared.global [%0], [%1], 16;" :: "r"(s), "l"(g));
}
static __device__ __forceinline__ void mma_f16(float* c, const uint32_t* a,
                                               uint32_t b0, uint32_t b1) {
    asm volatile(
        "mma.sync.aligned.m16n8k16.row.col.f32.f16.f16.f32 "
        "{%0,%1,%2,%3}, {%4,%5,%6,%7}, {%8,%9}, {%0,%1,%2,%3};"
        : "+f"(c[0]), "+f"(c[1]), "+f"(c[2]), "+f"(c[3])
        : "r"(a[0]), "r"(a[1]), "r"(a[2]), "r"(a[3]), "r"(b0), "r"(b1));
}

// ---- pre-pass 1: X fp32 -> fp16 flat (8 elems / thread-iter) ----
__global__ void __launch_bounds__(256) conv_x_kernel(const float* __restrict__ in,
                                                     uint4* __restrict__ out, int n8) {
    int i = blockIdx.x * blockDim.x + threadIdx.x;
    const int step = gridDim.x * blockDim.x;
    for (; i < n8; i += step) {
        const float4* p = reinterpret_cast<const float4*>(in) + 2 * (size_t)i;
        float4 v0 = p[0], v1 = p[1];
        uint4 r;
        r.x = packh2(v0.x, v0.y); r.y = packh2(v0.z, v0.w);
        r.z = packh2(v1.x, v1.y); r.w = packh2(v1.z, v1.w);
        out[i] = r;
    }
}

// ---- pre-pass 2: W fp32 [tb][ci][co] -> fp16 word [tb][ci/2][co] ----
__global__ void __launch_bounds__(256) conv_w_kernel(const float* __restrict__ in,
                                                     uint32_t* __restrict__ out, int ntot) {
    int i = blockIdx.x * blockDim.x + threadIdx.x;
    const int step = gridDim.x * blockDim.x;
    for (; i < ntot; i += step) {
        int co = i & 127;
        int cp = (i >> 7) & 63;
        int tb = i >> 13;                       // b*9 + tap, 0..143
        const float* s = in + (size_t)tb * 16384 + (size_t)(2 * cp) * 128 + co;
        out[i] = packh2(s[0], s[128]);
    }
}

__global__ void __launch_bounds__(256, 2) conv_mma_kernel(float* __restrict__ Out)
{
    extern __shared__ uint32_t smem[];
    const uint32_t sbase = (uint32_t)__cvta_generic_to_shared(smem);

    const int tid  = threadIdx.x;
    const int lane = tid & 31;
    const int warp = tid >> 5;
    const int wm   = warp & 3;     // warp tile rows: wm*32
    const int wn   = warp >> 2;    // warp tile cols: wn*64
    const int y = blockIdx.x;      // output row 0..125
    const int b = blockIdx.y;      // sample   0..15

    const __half*   Xb = g_Xh + (size_t)b * (128u * 128u * 128u);
    const uint32_t* Wb = g_Wc + (size_t)b * (9u * 64u * 128u);

    float acc[2][8][4];
    #pragma unroll
    for (int mi = 0; mi < 2; mi++)
        #pragma unroll
        for (int ni = 0; ni < 8; ni++)
            #pragma unroll
            for (int j = 0; j < 4; j++) acc[mi][ni][j] = 0.0f;

    // staging coords (constant): A: 2 x (row, 16B slot); B: 2 x (cp-row, 16B slot)
    const int arow = tid >> 2;           // +0, +64
    const int aslt = tid & 3;
    const int bcp  = tid >> 5;           // +0, +8
    const int bslt = tid & 31;

    // chunk k -> (ky, c0, kx): k = ky*12 + (c0/32)*3 + kx  (kx inner: X line reuse)
    auto issue_stage = [&](int k, int stg) {
        const int ky = k / 12, rem = k % 12;
        const int c0 = (rem / 3) * 32, kx = rem % 3;
        const uint32_t dst = sbase + (uint32_t)(stg * STAGE_WORDS * 4);
        const __half* Ap = Xb + (size_t)(y + ky) * (128 * 128) + c0 + aslt * 8;
        #pragma unroll
        for (int t = 0; t < 2; t++) {
            int r = arow + t * 64;
            int xi = r + kx; if (xi > 127) xi = 127;          // dead-row clamp
            cpasync16(dst + (uint32_t)((r * A_STRIDE + aslt * 4) * 4),
                      Ap + (size_t)xi * CIN);
        }
        const uint32_t* Bp = Wb + (size_t)((ky * 3 + kx) * 64 + (c0 >> 1)) * COUT + bslt * 4;
        #pragma unroll
        for (int t = 0; t < 2; t++) {
            int cp = bcp + t * 8;
            cpasync16(dst + (uint32_t)((A_WORDS + cp * B_STRIDE + bslt * 4) * 4),
                      Bp + (size_t)cp * COUT);
        }
    };

    issue_stage(0, 0);
    asm volatile("cp.async.commit_group;" ::: "memory");
    issue_stage(1, 1);
    asm volatile("cp.async.commit_group;" ::: "memory");

    for (int k = 0; k < 36; k++) {
        asm volatile("cp.async.wait_group 1;" ::: "memory");  // stage k resident
        __syncthreads();   // also: all warps done with buf[(k-1)%3] before refill

        if (k + 2 < 36) issue_stage(k + 2, (k + 2) % NSTAGE);
        asm volatile("cp.async.commit_group;" ::: "memory");

        const uint32_t* sA = smem + (k % NSTAGE) * STAGE_WORDS;
        const uint32_t* sB = sA + A_WORDS;

        #pragma unroll
        for (int kk = 0; kk < 2; kk++) {        // 2 x K=16 per 32-ci chunk
            const int k0w = kk * 8;             // word col in A
            const int cpb = kk * 8;             // cp row base in B
            uint32_t af[2][4];
            #pragma unroll
            for (int mi = 0; mi < 2; mi++) {
                const int r0 = wm * 32 + mi * 16 + (lane >> 2);
                const int c  = k0w + (lane & 3);
                af[mi][0] = sA[(r0    ) * A_STRIDE + c    ];
                af[mi][1] = sA[(r0 + 8) * A_STRIDE + c    ];
                af[mi][2] = sA[(r0    ) * A_STRIDE + c + 4];
                af[mi][3] = sA[(r0 + 8) * A_STRIDE + c + 4];
            }
            const int cpr = cpb + (lane & 3);
            const int bc  = wn * 64 + (lane >> 2);
            #pragma unroll
            for (int ni = 0; ni < 8; ni++) {
                uint32_t b0 = sB[(cpr    ) * B_STRIDE + bc + ni * 8];
                uint32_t b1 = sB[(cpr + 4) * B_STRIDE + bc + ni * 8];
                mma_f16(acc[0][ni], af[0], b0, b1);
                mma_f16(acc[1][ni], af[1], b0, b1);
            }
        }
    }

    // ---- epilogue: registers -> Out, skipping dead x rows (>=126) ----
    float* Ob = Out + ((size_t)b * OH + y) * (OH * (size_t)COUT);
    #pragma unroll
    for (int mi = 0; mi < 2; mi++) {
        const int row0 = wm * 32 + mi * 16 + (lane >> 2);
        #pragma unroll
        for (int ni = 0; ni < 8; ni++) {
            const int col = wn * 64 + ni * 8 + 2 * (lane & 3);
            if (row0 < OH) {
                float2 v = make_float2(acc[mi][ni][0], acc[mi][ni][1]);
                *reinterpret_cast<float2*>(Ob + (size_t)row0 * COUT + col) = v;
            }
            if (row0 + 8 < OH) {
                float2 v = make_float2(acc[mi][ni][2], acc[mi][ni][3]);
                *reinterpret_cast<float2*>(Ob + (size_t)(row0 + 8) * COUT + col) = v;
            }
        }
    }
}

extern "C" void kernel_launch(void* const* d_in, const int* in_sizes, int n_in,
                              void* d_out, int out_size) {
    (void)in_sizes; (void)n_in; (void)out_size;
    const float* X  = (const float*)d_in[0];
    const float* Wt = (const float*)d_in[1];
    float* out = (float*)d_out;

    void *xh, *wc;
    cudaGetSymbolAddress(&xh, g_Xh);
    cudaGetSymbolAddress(&wc, g_Wc);

    conv_x_kernel<<<2048, 256>>>(X, (uint4*)xh, (16 * 128 * 128 * 128) / 8);
    conv_w_kernel<<<1024, 256>>>(Wt, (uint32_t*)wc, 16 * 9 * 64 * 128);

    cudaFuncSetAttribute(conv_mma_kernel,
                         cudaFuncAttributeMaxDynamicSharedMemorySize, SMEM_BYTES);
    conv_mma_kernel<<<dim3(OH, 16), 256, SMEM_BYTES>>>(out);
}